// round 6
// baseline (speedup 1.0000x reference)
#include <cuda_runtime.h>

// ResidualEmbedding: per-frame Burg LPC (order 12) residual, sign-modulated embed.
// R6: two frames/warp (16 lanes, 10 contiguous samples each), plus:
//  - Burg state packed in f32x2; dot / den-init / t,u updates use fma.rn.f32x2.
//  - Direct vectorized global I/O (LDG.64/STG.64, lane-contiguous) - no transposes.
//  - Shared memory only for the 12-sample FIR halo (STS.64/LDS.64).
//  - Zero-propagation invariant keeps all reductions mask-free.

namespace {

constexpr int FRAME   = 160;
constexpr int KFR     = 15;
constexpr int ORDER   = 12;
constexpr int BATCH   = 4096;
constexpr int NFRAMES = BATCH * KFR;     // 61440
constexpr int WPB     = 8;               // warps per block (16 frames/block)
constexpr int THREADS = WPB * 32;
constexpr int ROW     = 184;             // 12 pad + 160 + slack (floats)
constexpr unsigned FULL = 0xffffffffu;

using ull = unsigned long long;

__device__ __forceinline__ ull pk(float x, float y) {
    ull r; asm("mov.b64 %0, {%1, %2};" : "=l"(r) : "f"(x), "f"(y)); return r;
}
__device__ __forceinline__ void up2(ull v, float& x, float& y) {
    asm("mov.b64 {%0, %1}, %2;" : "=f"(x), "=f"(y) : "l"(v));
}
__device__ __forceinline__ ull fma2(ull a, ull b, ull c) {
    ull r; asm("fma.rn.f32x2 %0, %1, %2, %3;" : "=l"(r) : "l"(a), "l"(b), "l"(c)); return r;
}

// reduce over each 16-lane half independently (both frames at once)
__device__ __forceinline__ float half_sum(float v) {
#pragma unroll
    for (int o = 8; o > 0; o >>= 1) v += __shfl_xor_sync(FULL, v, o);
    return v;
}

__global__ __launch_bounds__(THREADS) void burg_residual_kernel(
    const int*   __restrict__ bits,
    const float* __restrict__ pcm,
    const float* __restrict__ alpha_p,
    float*       __restrict__ out)
{
    const int warp   = threadIdx.x >> 5;
    const int lane   = threadIdx.x & 31;
    const int frame0 = (blockIdx.x * WPB + warp) * 2;   // exact grid

    const int half = lane >> 4;
    const int lh   = lane & 15;
    const int jb   = 10 * lh;

    __shared__ float Xs[WPB][2][ROW];
    float* __restrict__ P = &Xs[warp][half][0];          // sample j at P[12+j]

    // ---- Direct vectorized load: lane's own 10 contiguous samples ----
    const float* __restrict__ src =
        pcm + (long long)frame0 * FRAME + half * FRAME + jb;
    float x[10];
    {
        const float2* s2 = (const float2*)src;           // 40B lane offset: 8B aligned
#pragma unroll
        for (int k = 0; k < 5; ++k) {
            const float2 v = s2[k];
            x[2 * k] = v.x; x[2 * k + 1] = v.y;
        }
    }

    // stash raw samples (+ zero halo) in shared for the FIR windows
    {
        float2* Pd = (float2*)(P + 12 + jb);
#pragma unroll
        for (int k = 0; k < 5; ++k) Pd[k] = make_float2(x[2 * k], x[2 * k + 1]);
        if (lh < 6) ((float2*)P)[lh] = make_float2(0.f, 0.f);   // P[0..11] = 0
    }

    // ---- Window (np.hanning: 0.5 - 0.5*cos(2*pi*j/159)) ----
    float xw[10];
#pragma unroll
    for (int c = 0; c < 10; ++c) {
        const float w = 0.5f - 0.5f * __cosf((6.283185307179586f / 159.0f) * (float)(jb + c));
        xw[c] = x[c] * w;
    }

    // ---- Init packed state: b[j]=xw[j], f[j]=xw[j+1]; j=159 entries = 0 ----
    const float nxt = __shfl_sync(FULL, xw[0], lane + 1);
    const float f9  = (lh == 15) ? 0.f : nxt;
    const float b9  = (lh == 15) ? 0.f : xw[9];
    ull f2[5], b2[5];
    f2[0] = pk(xw[1], xw[2]); f2[1] = pk(xw[3], xw[4]); f2[2] = pk(xw[5], xw[6]);
    f2[3] = pk(xw[7], xw[8]); f2[4] = pk(xw[9], f9);
    b2[0] = pk(xw[0], xw[1]); b2[1] = pk(xw[2], xw[3]); b2[2] = pk(xw[4], xw[5]);
    b2[3] = pk(xw[6], xw[7]); b2[4] = pk(xw[8], b9);

    float den;
    {
        ull acc2 = 0ull;
#pragma unroll
        for (int k = 0; k < 5; ++k) {
            acc2 = fma2(f2[k], f2[k], acc2);
            acc2 = fma2(b2[k], b2[k], acc2);
        }
        float px, py; up2(acc2, px, py);
        den = half_sum(px + py);
    }

    float a[ORDER + 1];
    a[0] = 1.f;
#pragma unroll
    for (int k = 1; k <= ORDER; ++k) a[k] = 0.f;

    // ---- Burg recursion. Invariant at iter i entry: f[j]=b[j]=0 for j>=159-i ----
#pragma unroll
    for (int i = 0; i < ORDER; ++i) {
        ull acc2 = 0ull;
#pragma unroll
        for (int k = 0; k < 5; ++k) acc2 = fma2(f2[k], b2[k], acc2);
        float px, py; up2(acc2, px, py);
        const float s = half_sum(px + py);
        const float r = __fdividef(-2.f * s, den);
        const ull  r2 = pk(r, r);

        ull t2[5], u2[5];
#pragma unroll
        for (int k = 0; k < 5; ++k) {
            t2[k] = fma2(r2, b2[k], f2[k]);   // new f (pre-trim)
            u2[k] = fma2(r2, f2[k], b2[k]);   // new b (pre-trim)
        }

        // den_{i+1} = (1-r^2)*den - u[158-i]^2 - t[0]^2
        const int jl = 158 - i;               // compile-time under unroll
        const int Ll = jl / 10, cl = jl % 10;
        float t0x, t0y; up2(t2[0], t0x, t0y);
        const float t0 = __shfl_sync(FULL, t0x, half << 4);
        float ux, uy;  up2(u2[cl >> 1], ux, uy);
        const float uc = __shfl_sync(FULL, (cl & 1) ? uy : ux, (half << 4) | Ll);
        den = (1.f - r * r) * den - uc * uc - t0 * t0;

        // f' = shift-by-1(t)
        float t[10];
#pragma unroll
        for (int k = 0; k < 5; ++k) up2(t2[k], t[2 * k], t[2 * k + 1]);
        float tn = __shfl_sync(FULL, t[0], lane + 1);
        if (lh == 15) tn = 0.f;
        f2[0] = pk(t[1], t[2]); f2[1] = pk(t[3], t[4]); f2[2] = pk(t[5], t[6]);
        f2[3] = pk(t[7], t[8]); f2[4] = pk(t[9], tn);

        // b' = u with the newly-invalid element (j = 158-i) zeroed
#pragma unroll
        for (int k = 0; k < 5; ++k) b2[k] = u2[k];
        {
            float vx, vy; up2(u2[cl >> 1], vx, vy);
            const ull z = (cl & 1) ? pk(vx, 0.f) : pk(0.f, vy);
            if (lh == Ll) b2[cl >> 1] = z;
        }

        // a[:i+2] += r * reverse(a[:i+2])  -- pairwise in place
#pragma unroll
        for (int k = 0; 2 * k <= i + 1; ++k) {
            const int k2 = i + 1 - k;
            if (k2 == k) {
                a[k] = a[k] + r * a[k];
            } else {
                const float tmp = a[k];
                a[k]  = fmaf(r, a[k2], a[k]);
                a[k2] = fmaf(r, tmp,  a[k2]);
            }
        }
    }

    // ---- FIR on raw samples: 22-float register window (vectorized LDS) ----
    __syncwarp();   // halo STS visible
    float xf[22];   // X[jb-12 .. jb+9]
    {
        const float2* W = (const float2*)(P + jb);   // = &P[12 + jb - 12]
#pragma unroll
        for (int k = 0; k < 11; ++k) {
            const float2 v = W[k];
            xf[2 * k] = v.x; xf[2 * k + 1] = v.y;
        }
    }

    const int fr = frame0 + half;
    const float sgn  = 2.f * (float)__ldg(&bits[fr]) - 1.f;
    const float coef = __ldg(alpha_p) * sgn;

    float o[10];
#pragma unroll
    for (int c = 0; c < 10; ++c) {
        float acc = a[0] * xf[12 + c];
#pragma unroll
        for (int k = 1; k <= ORDER; ++k)
            acc = fmaf(a[k], xf[12 + c - k], acc);
        o[c] = fmaf(coef, acc, xf[12 + c]);
    }

    // ---- Direct vectorized store (dense 40B-stride float2 lanes) ----
    float* __restrict__ dst = out + (long long)frame0 * FRAME + half * FRAME + jb;
    float2* d2 = (float2*)dst;
#pragma unroll
    for (int k = 0; k < 5; ++k) d2[k] = make_float2(o[2 * k], o[2 * k + 1]);
}

} // namespace

extern "C" void kernel_launch(void* const* d_in, const int* in_sizes, int n_in,
                              void* d_out, int out_size)
{
    const int*   bits  = (const int*)  d_in[0];
    const float* pcm   = (const float*)d_in[1];
    const float* alpha = (const float*)d_in[2];
    float*       out   = (float*)d_out;

    const int grid = NFRAMES / (WPB * 2);   // 3840 blocks
    burg_residual_kernel<<<grid, THREADS>>>(bits, pcm, alpha, out);
}

// round 7
// speedup vs baseline: 1.3114x; 1.3114x over previous
#include <cuda_runtime.h>

// ResidualEmbedding: per-frame Burg LPC (order 12) residual, sign-modulated embed.
// R7: FOUR frames per warp, 8 lanes per frame, 20 contiguous samples per lane.
//  - 3-step xor butterfly (4/2/1) reduces all 4 frames in one instruction stream.
//  - Scalar math (R6 lesson: f32x2 repacking cost > benefit), in-place f/b update.
//  - LDG.128 / STS.128 / LDS.128 / STG.128 vectorized data movement.
//  - Zero-propagation invariant: all reductions mask-free.

namespace {

constexpr int FRAME   = 160;
constexpr int ORDER   = 12;
constexpr int NFRAMES = 4096 * 15;       // 61440
constexpr int WPB     = 8;               // warps per block (32 frames/block)
constexpr int THREADS = WPB * 32;
constexpr int ROW     = 176;             // 12 halo + 160 + 4 pad (floats, 16B-aligned)
constexpr unsigned FULL = 0xffffffffu;

// reduce over each 8-lane group independently (4 frames at once)
__device__ __forceinline__ float grp_sum(float v) {
#pragma unroll
    for (int o = 4; o > 0; o >>= 1) v += __shfl_xor_sync(FULL, v, o);
    return v;
}

__global__ __launch_bounds__(THREADS) void burg_residual_kernel(
    const int*   __restrict__ bits,
    const float* __restrict__ pcm,
    const float* __restrict__ alpha_p,
    float*       __restrict__ out)
{
    const int warp   = threadIdx.x >> 5;
    const int lane   = threadIdx.x & 31;
    const int frame0 = (blockIdx.x * WPB + warp) * 4;   // exact grid
    const int sub    = lane >> 3;        // frame within warp
    const int lh     = lane & 7;         // lane within frame
    const int jb     = 20 * lh;          // my contiguous j-range start

    __shared__ float Xs[WPB][4][ROW];
    float* __restrict__ P = &Xs[warp][sub][0];          // sample j at P[12+j]

    // ---- Vectorized load: 20 contiguous samples (5 x LDG.128) ----
    const float* __restrict__ src = pcm + (long long)(frame0 + sub) * FRAME + jb;
    float x[20];
    {
        const float4* s4 = (const float4*)src;
#pragma unroll
        for (int k = 0; k < 5; ++k) {
            const float4 v = s4[k];
            x[4*k] = v.x; x[4*k+1] = v.y; x[4*k+2] = v.z; x[4*k+3] = v.w;
        }
    }
    {   // stash raw samples + zero halo (P[0..11]) for FIR
        float4* Pd = (float4*)(P + 12 + jb);
#pragma unroll
        for (int k = 0; k < 5; ++k)
            Pd[k] = make_float4(x[4*k], x[4*k+1], x[4*k+2], x[4*k+3]);
        if (lh < 3) ((float4*)P)[lh] = make_float4(0.f, 0.f, 0.f, 0.f);
    }

    // ---- Window (np.hanning: 0.5 - 0.5*cos(2*pi*j/159)) ----
    float xw[20];
#pragma unroll
    for (int c = 0; c < 20; ++c) {
        const float w = 0.5f - 0.5f * __cosf((6.283185307179586f / 159.0f) * (float)(jb + c));
        xw[c] = x[c] * w;
    }

    // ---- Init: b[j]=xw[j], f[j]=xw[j+1] (valid j<=158); j=159 entries = 0 ----
    float f[20], b[20];
#pragma unroll
    for (int c = 0; c < 20; ++c) b[c] = xw[c];
#pragma unroll
    for (int c = 0; c < 19; ++c) f[c] = xw[c + 1];
    {
        const float nxt = __shfl_sync(FULL, xw[0], lane + 1);
        f[19] = (lh == 7) ? 0.f : nxt;
    }
    if (lh == 7) b[19] = 0.f;

    float den;
    {
        float p0 = 0.f, p1 = 0.f;
#pragma unroll
        for (int c = 0; c < 20; c += 2) {
            p0 = fmaf(f[c],   f[c],   fmaf(b[c],   b[c],   p0));
            p1 = fmaf(f[c+1], f[c+1], fmaf(b[c+1], b[c+1], p1));
        }
        den = grp_sum(p0 + p1);
    }

    float a[ORDER + 1];
    a[0] = 1.f;
#pragma unroll
    for (int k = 1; k <= ORDER; ++k) a[k] = 0.f;

    // ---- Burg recursion. Invariant at iter i entry: f[j]=b[j]=0 for j>=159-i ----
#pragma unroll
    for (int i = 0; i < ORDER; ++i) {
        float p0 = 0.f, p1 = 0.f;
#pragma unroll
        for (int c = 0; c < 20; c += 2) {
            p0 = fmaf(f[c],   b[c],   p0);
            p1 = fmaf(f[c+1], b[c+1], p1);
        }
        const float s = grp_sum(p0 + p1);
        const float r = __fdividef(-2.f * s, den);

        // in-place: f <- t = f + r*b ; b <- u = b + r*f_old
#pragma unroll
        for (int c = 0; c < 20; ++c) {
            const float fo = f[c];
            f[c] = fmaf(r, b[c], f[c]);
            b[c] = fmaf(r, fo,   b[c]);
        }

        // den_{i+1} = (1-r^2)*den - b_new[158-i]^2 - f_new[0]^2
        const int jl = 158 - i, Ll = jl / 20, cl = jl % 20;   // compile-time
        const float nf19 = __shfl_sync(FULL, f[0], lane + 1); // for the shift
        const float t0   = __shfl_sync(FULL, f[0], lane & ~7);
        const float ub   = __shfl_sync(FULL, b[cl], (lane & ~7) | Ll);
        den = (1.f - r * r) * den - ub * ub - t0 * t0;

        // f' = shift-by-1(f); b': zero newly-invalid element
#pragma unroll
        for (int c = 0; c < 19; ++c) f[c] = f[c + 1];
        f[19] = (lh == 7) ? 0.f : nf19;
        if (lh == Ll) b[cl] = 0.f;

        // a[:i+2] += r * reverse(a[:i+2])  -- pairwise in place
#pragma unroll
        for (int k = 0; 2 * k <= i + 1; ++k) {
            const int k2 = i + 1 - k;
            if (k2 == k) {
                a[k] = a[k] + r * a[k];
            } else {
                const float tmp = a[k];
                a[k]  = fmaf(r, a[k2], a[k]);
                a[k2] = fmaf(r, tmp,  a[k2]);
            }
        }
    }

    // ---- FIR on raw samples: 32-float register window (8 x LDS.128) ----
    __syncwarp();   // halo/sample STS visible across the group
    float xf[32];   // X[jb-12 .. jb+19]
    {
        const float4* W = (const float4*)(P + jb);   // = &P[12 + jb - 12]
#pragma unroll
        for (int k = 0; k < 8; ++k) {
            const float4 v = W[k];
            xf[4*k] = v.x; xf[4*k+1] = v.y; xf[4*k+2] = v.z; xf[4*k+3] = v.w;
        }
    }

    const float sgn  = 2.f * (float)__ldg(&bits[frame0 + sub]) - 1.f;
    const float coef = __ldg(alpha_p) * sgn;

    float o[20];
#pragma unroll
    for (int c = 0; c < 20; ++c) {
        float acc = a[0] * xf[12 + c];
#pragma unroll
        for (int k = 1; k <= ORDER; ++k)
            acc = fmaf(a[k], xf[12 + c - k], acc);
        o[c] = fmaf(coef, acc, xf[12 + c]);
    }

    // ---- Vectorized store (5 x STG.128) ----
    float* __restrict__ dst = out + (long long)(frame0 + sub) * FRAME + jb;
    float4* d4 = (float4*)dst;
#pragma unroll
    for (int k = 0; k < 5; ++k)
        d4[k] = make_float4(o[4*k], o[4*k+1], o[4*k+2], o[4*k+3]);
}

} // namespace

extern "C" void kernel_launch(void* const* d_in, const int* in_sizes, int n_in,
                              void* d_out, int out_size)
{
    const int*   bits  = (const int*)  d_in[0];
    const float* pcm   = (const float*)d_in[1];
    const float* alpha = (const float*)d_in[2];
    float*       out   = (float*)d_out;

    const int grid = NFRAMES / (WPB * 4);   // 1920 blocks
    burg_residual_kernel<<<grid, THREADS>>>(bits, pcm, alpha, out);
}